// round 13
// baseline (speedup 1.0000x reference)
#include <cuda_runtime.h>
#include <cuda_bf16.h>
#include <cstdint>

using bf16 = __nv_bfloat16;

// ---------------------------------------------------------------------------
// Problem constants
// ---------------------------------------------------------------------------
constexpr int HH   = 128;
constexpr int WW   = 128;
constexpr int CC   = 192;
constexpr int NHH  = 6;
constexpr int HDD  = 32;
constexpr int WS   = 8;
constexpr int SH   = 4;
constexpr int NT   = 64;
constexpr int NWIN = 2048;
constexpr int MROWS = 131072;
constexpr float SCALE_F = 0.17677669529663689f;

// ---------------------------------------------------------------------------
// Scratch (device globals, only referenced from device code)
// ---------------------------------------------------------------------------
__device__ bf16  g_hwin[(size_t)MROWS * CC];
__device__ bf16  g_qb[(size_t)NWIN * NHH * NT * HDD];  // q*scale [wh][t][d]
__device__ bf16  g_kb[(size_t)NWIN * NHH * NT * HDD];  // k       [wh][t][d]
__device__ bf16  g_vb[(size_t)NWIN * NHH * NT * HDD];  // v       [wh][t][d]
__device__ bf16  g_att[(size_t)MROWS * CC];
__device__ float g_xmid[(size_t)MROWS * CC];
__device__ bf16  g_ln2[(size_t)MROWS * CC];
__device__ bf16  g_h1[(size_t)MROWS * 4 * CC];
__device__ float g_bm[4 * NHH * NT * NT];              // fused bias+mask, 4 window types
__device__ bf16  g_wqkv[576 * 192];
__device__ bf16  g_wproj[192 * 192];
__device__ bf16  g_wfc1[768 * 192];
__device__ bf16  g_wfc2[192 * 768];

// ---------------------------------------------------------------------------
// Helpers
// ---------------------------------------------------------------------------
__device__ __forceinline__ uint32_t smem_u32(const void* p) {
    return (uint32_t)__cvta_generic_to_shared(p);
}
__device__ __forceinline__ void cpasync16(uint32_t s, const void* g) {
    asm volatile("cp.async.cg.shared.global [%0], [%1], 16;" :: "r"(s), "l"(g));
}
__device__ __forceinline__ void ldsm4(uint32_t* r, uint32_t a) {
    asm volatile("ldmatrix.sync.aligned.m8n8.x4.shared.b16 {%0,%1,%2,%3}, [%4];"
        : "=r"(r[0]), "=r"(r[1]), "=r"(r[2]), "=r"(r[3]) : "r"(a));
}
__device__ __forceinline__ void ldsm4t(uint32_t* r, uint32_t a) {
    asm volatile("ldmatrix.sync.aligned.m8n8.x4.trans.shared.b16 {%0,%1,%2,%3}, [%4];"
        : "=r"(r[0]), "=r"(r[1]), "=r"(r[2]), "=r"(r[3]) : "r"(a));
}
__device__ __forceinline__ void mma16816(float* c, const uint32_t* a, const uint32_t* b) {
    asm volatile("mma.sync.aligned.m16n8k16.row.col.f32.bf16.bf16.f32 "
        "{%0,%1,%2,%3}, {%4,%5,%6,%7}, {%8,%9}, {%0,%1,%2,%3};"
        : "+f"(c[0]), "+f"(c[1]), "+f"(c[2]), "+f"(c[3])
        : "r"(a[0]), "r"(a[1]), "r"(a[2]), "r"(a[3]), "r"(b[0]), "r"(b[1]));
}
__device__ __forceinline__ uint32_t packbf(float a, float b) {
    __nv_bfloat162 h = __float22bfloat162_rn(make_float2(a, b));
    return *(uint32_t*)&h;
}

// ---------------------------------------------------------------------------
// Setup: weight conversion + fused bias+mask tables (4 window types)
// ---------------------------------------------------------------------------
__global__ void setup_kernel(const float* __restrict__ qkv,
                             const float* __restrict__ proj,
                             const float* __restrict__ fc1,
                             const float* __restrict__ fc2,
                             const float* __restrict__ rpb)
{
    int i = blockIdx.x * blockDim.x + threadIdx.x;
    if (i < 576 * 192) g_wqkv[i]  = __float2bfloat16(qkv[i]);
    if (i < 192 * 192) g_wproj[i] = __float2bfloat16(proj[i]);
    if (i < 768 * 192) { g_wfc1[i] = __float2bfloat16(fc1[i]);
                         g_wfc2[i] = __float2bfloat16(fc2[i]); }
    if (i < 4 * NHH * NT * NT) {                 // 98304 entries
        int type = i / (NHH * NT * NT);
        int rem  = i - type * (NHH * NT * NT);
        int nh   = rem >> 12;
        int rc   = rem & 4095, r = rc >> 6, c = rc & 63;
        int dy = (r >> 3) - (c >> 3) + 7;
        int dx = (r & 7) - (c & 7) + 7;
        float b = rpb[(dy * 15 + dx) * NHH + nh];
        // labels: window type bit1 = last row-block (wy==15), bit0 = last col (wx==15)
        int tr = type >> 1, tc = type & 1;
        int lyr = tr ? (((r >> 3) < 4) ? 1 : 2) : 0;
        int lxr = tc ? (((r & 7) < 4) ? 1 : 2) : 0;
        int lyc = tr ? (((c >> 3) < 4) ? 1 : 2) : 0;
        int lxc = tc ? (((c & 7) < 4) ? 1 : 2) : 0;
        if (lyr * 3 + lxr != lyc * 3 + lxc) b -= 100.f;
        g_bm[i] = b;
    }
}

// ---------------------------------------------------------------------------
// LayerNorm, float2-vectorized.
// LMODE 0: gather shift+window from x -> g_hwin; LMODE 1: g_xmid -> g_ln2
// ---------------------------------------------------------------------------
template<int LMODE>
__global__ void ln_kernel(const float* __restrict__ xin,
                          const float* __restrict__ gam,
                          const float* __restrict__ bet)
{
    int warp = (blockIdx.x * blockDim.x + threadIdx.x) >> 5;
    int lane = threadIdx.x & 31;
    if (warp >= MROWS) return;

    const float* in = (LMODE == 0) ? xin : g_xmid;
    bf16* out       = (LMODE == 0) ? g_hwin : g_ln2;

    int src = warp;
    if (LMODE == 0) {
        int w = warp >> 6, t = warp & 63;
        int bb = w >> 8, wi = w & 255;
        int wy = wi >> 4, wx = wi & 15;
        int ty = t >> 3, tx = t & 7;
        int oy = (wy * 8 + ty + SH) & 127;
        int ox = (wx * 8 + tx + SH) & 127;
        src = (bb << 14) + (oy << 7) + ox;
    }
    const float2* row = (const float2*)(in + (size_t)src * CC);
    float2 v[3];
    float s = 0.f, s2 = 0.f;
#pragma unroll
    for (int i = 0; i < 3; i++) {
        v[i] = row[lane + 32 * i];
        s  += v[i].x + v[i].y;
        s2 += v[i].x * v[i].x + v[i].y * v[i].y;
    }
#pragma unroll
    for (int off = 16; off; off >>= 1) {
        s  += __shfl_xor_sync(0xffffffffu, s,  off);
        s2 += __shfl_xor_sync(0xffffffffu, s2, off);
    }
    float mu  = s * (1.f / CC);
    float var = s2 * (1.f / CC) - mu * mu;
    float inv = rsqrtf(var + 1e-5f);
    __nv_bfloat162* orow = (__nv_bfloat162*)(out + (size_t)warp * CC);
    const float2* g2 = (const float2*)gam;
    const float2* b2 = (const float2*)bet;
#pragma unroll
    for (int i = 0; i < 3; i++) {
        int c2 = lane + 32 * i;
        float2 gg = g2[c2], bb = b2[c2];
        float o0 = (v[i].x - mu) * inv * gg.x + bb.x;
        float o1 = (v[i].y - mu) * inv * gg.y + bb.y;
        orow[c2] = __float22bfloat162_rn(make_float2(o0, o1));
    }
}

// ---------------------------------------------------------------------------
// HMMA GEMM, BK=64, 2-stage cp.async smem pipeline + 2-deep register
// fragment pipeline, vectorized epilogue (proven R12).
// MODE 0: A=g_hwin,W=g_wqkv  -> q(scaled)/k/v (bf16, all [t][d])
// MODE 1: A=g_ln2, W=g_wfc1  -> leaky relu -> g_h1 (bf16)
// MODE 2: A=g_h1,  W=g_wfc2  -> + g_xmid -> Cext (fp32)
// MODE 3: A=g_att, W=g_wproj -> window-reverse scatter, + x -> g_xmid
// ---------------------------------------------------------------------------
template<int MODE, int KDIM, int NDIM>
__global__ void __launch_bounds__(128) gemm_mma(const float* __restrict__ bias,
                                                const float* __restrict__ Rext,
                                                float* __restrict__ Cext)
{
    const bf16* A = (MODE == 0) ? g_hwin : (MODE == 1) ? g_ln2 :
                    (MODE == 2) ? g_h1   : g_att;
    const bf16* W = (MODE == 0) ? g_wqkv : (MODE == 1) ? g_wfc1 :
                    (MODE == 2) ? g_wfc2 : g_wproj;

    __shared__ __align__(16) bf16 As[2][128][72];
    __shared__ __align__(16) bf16 Bs[2][64][72];

    int m0 = blockIdx.y * 128, n0 = blockIdx.x * 64;
    int tid = threadIdx.x, lane = tid & 31, warp = tid >> 5;

    constexpr int NCH = KDIM / 64;

    auto prefetch = [&](int ch, int buf) {
        int kt = ch * 64;
#pragma unroll
        for (int i = 0; i < 8; i++) {
            int idx = tid + i * 128;
            int r = idx >> 3, c8 = (idx & 7) * 8;
            cpasync16(smem_u32(&As[buf][r][c8]),
                      &A[(size_t)(m0 + r) * KDIM + kt + c8]);
        }
#pragma unroll
        for (int i = 0; i < 4; i++) {
            int idx = tid + i * 128;
            int r = idx >> 3, c8 = (idx & 7) * 8;
            cpasync16(smem_u32(&Bs[buf][r][c8]),
                      &W[(size_t)(n0 + r) * KDIM + kt + c8]);
        }
    };

    float acc[2][8][4] = {};

    prefetch(0, 0);
    asm volatile("cp.async.commit_group;");

    uint32_t afr[2][2][4];
    uint32_t bfr[2][8][2];

    for (int ch = 0; ch < NCH; ch++) {
        int buf = ch & 1;
        if (ch + 1 < NCH) {
            prefetch(ch + 1, buf ^ 1);
            asm volatile("cp.async.commit_group;");
            asm volatile("cp.async.wait_group 1;");
        } else {
            asm volatile("cp.async.wait_group 0;");
        }
        __syncthreads();

        {
#pragma unroll
            for (int mi = 0; mi < 2; mi++)
                ldsm4(afr[0][mi], smem_u32(
                    &As[buf][warp * 32 + mi * 16 + (lane & 15)][((lane & 16) >> 1)]));
#pragma unroll
            for (int p = 0; p < 4; p++) {
                uint32_t t4[4];
                ldsm4(t4, smem_u32(
                    &Bs[buf][p * 16 + ((lane & 16) >> 1) + (lane & 7)][(lane & 8)]));
                bfr[0][2*p  ][0] = t4[0]; bfr[0][2*p  ][1] = t4[1];
                bfr[0][2*p+1][0] = t4[2]; bfr[0][2*p+1][1] = t4[3];
            }
        }

#pragma unroll
        for (int ks = 0; ks < 4; ks++) {
            int cur = ks & 1, nxt = cur ^ 1;
            if (ks < 3) {
                int kk = (ks + 1) * 16;
#pragma unroll
                for (int mi = 0; mi < 2; mi++)
                    ldsm4(afr[nxt][mi], smem_u32(
                        &As[buf][warp * 32 + mi * 16 + (lane & 15)][kk + ((lane & 16) >> 1)]));
#pragma unroll
                for (int p = 0; p < 4; p++) {
                    uint32_t t4[4];
                    ldsm4(t4, smem_u32(
                        &Bs[buf][p * 16 + ((lane & 16) >> 1) + (lane & 7)][kk + (lane & 8)]));
                    bfr[nxt][2*p  ][0] = t4[0]; bfr[nxt][2*p  ][1] = t4[1];
                    bfr[nxt][2*p+1][0] = t4[2]; bfr[nxt][2*p+1][1] = t4[3];
                }
            }
#pragma unroll
            for (int mi = 0; mi < 2; mi++)
#pragma unroll
                for (int nj = 0; nj < 8; nj++)
                    mma16816(acc[mi][nj], afr[cur][mi], bfr[cur][nj]);
        }
        __syncthreads();
    }

    // Vectorized epilogue: pairs (c[2h],c[2h+1]) = (m,n),(m,n+1).
    int g = lane >> 2, t2 = (lane & 3) * 2;
#pragma unroll
    for (int nj = 0; nj < 8; nj++) {
        int n = n0 + nj * 8 + t2;
        float2 bv = *(const float2*)&bias[n];
#pragma unroll
        for (int mi = 0; mi < 2; mi++)
#pragma unroll
            for (int h = 0; h < 2; h++) {
                int m = m0 + warp * 32 + mi * 16 + g + h * 8;
                float v0 = acc[mi][nj][2 * h]     + bv.x;
                float v1 = acc[mi][nj][2 * h + 1] + bv.y;
                if (MODE == 0) {
                    int s   = n / 192;
                    int rem = n - s * 192;
                    int nh  = rem >> 5, d = rem & 31;
                    int w = m >> 6, t = m & 63;
                    size_t off = ((size_t)(w * NHH + nh) * NT + t) * HDD + d;
                    if (s == 0) {
                        *(__nv_bfloat162*)&g_qb[off] =
                            __float22bfloat162_rn(make_float2(v0 * SCALE_F, v1 * SCALE_F));
                    } else if (s == 1) {
                        *(__nv_bfloat162*)&g_kb[off] =
                            __float22bfloat162_rn(make_float2(v0, v1));
                    } else {
                        *(__nv_bfloat162*)&g_vb[off] =
                            __float22bfloat162_rn(make_float2(v0, v1));
                    }
                } else if (MODE == 1) {
                    v0 = v0 > 0.f ? v0 : 0.2f * v0;
                    v1 = v1 > 0.f ? v1 : 0.2f * v1;
                    *(__nv_bfloat162*)&g_h1[(size_t)m * NDIM + n] =
                        __float22bfloat162_rn(make_float2(v0, v1));
                } else if (MODE == 2) {
                    size_t o = (size_t)m * NDIM + n;
                    float2 r2 = *(const float2*)&g_xmid[o];
                    *(float2*)&Cext[o] = make_float2(r2.x + v0, r2.y + v1);
                } else {
                    int w = m >> 6, t = m & 63;
                    int bb = w >> 8, wi = w & 255;
                    int wy = wi >> 4, wx = wi & 15;
                    int ty2 = t >> 3, tx2 = t & 7;
                    int oy = (wy * 8 + ty2 + SH) & 127;
                    int ox = (wx * 8 + tx2 + SH) & 127;
                    size_t orow = ((size_t)bb << 14) + (oy << 7) + ox;
                    size_t o = orow * NDIM + n;
                    float2 r2 = *(const float2*)&Rext[o];
                    *(float2*)&g_xmid[o] = make_float2(r2.x + v0, r2.y + v1);
                }
            }
    }
}

// ---------------------------------------------------------------------------
// Tensor-core attention.  V stored [t][d]; PV B-frags via ldmatrix.trans.
// Bias+mask fused table indexed by window type.  cp.async loads.
// ---------------------------------------------------------------------------
__global__ void attn_mma()
{
    int wh = blockIdx.x;
    int w  = wh / NHH;
    int wi = w & 255;
    int nh = wh - w * NHH;
    int type = (((wi >> 4) == 15) ? 2 : 0) + (((wi & 15) == 15) ? 1 : 0);

    __shared__ __align__(16) bf16 Qs[64][40];
    __shared__ __align__(16) bf16 Ks[64][40];
    __shared__ __align__(16) bf16 Vs[64][40];

    int tid = threadIdx.x, lane = tid & 31, warp = tid >> 5;
    size_t base = (size_t)wh * NT * HDD;

#pragma unroll
    for (int i = 0; i < 2; i++) {
        int idx = tid + i * 128;
        int r = idx >> 2, c8 = (idx & 3) * 8;
        cpasync16(smem_u32(&Qs[r][c8]), &g_qb[base + r * HDD + c8]);
        cpasync16(smem_u32(&Ks[r][c8]), &g_kb[base + r * HDD + c8]);
        cpasync16(smem_u32(&Vs[r][c8]), &g_vb[base + r * HDD + c8]);
    }
    asm volatile("cp.async.commit_group;");
    asm volatile("cp.async.wait_group 0;");
    __syncthreads();

    int mrow = warp * 16;

    // ---- S = Q K^T ----
    uint32_t aq[2][4];
#pragma unroll
    for (int kc = 0; kc < 2; kc++)
        ldsm4(aq[kc], smem_u32(
            &Qs[mrow + (lane & 15)][kc * 16 + ((lane & 16) >> 1)]));

    float sacc[8][4] = {};
#pragma unroll
    for (int kc = 0; kc < 2; kc++)
#pragma unroll
        for (int p = 0; p < 4; p++) {
            uint32_t t4[4];
            ldsm4(t4, smem_u32(
                &Ks[p * 16 + ((lane & 16) >> 1) + (lane & 7)][kc * 16 + (lane & 8)]));
            mma16816(sacc[2 * p],     aq[kc], t4);
            mma16816(sacc[2 * p + 1], aq[kc], t4 + 2);
        }

    // ---- fused bias+mask + softmax ----
    int g = lane >> 2, tq = lane & 3;
    int r0 = mrow + g, r1 = r0 + 8;
    const float* bm = g_bm + (size_t)(type * NHH + nh) * NT * NT;
    const float2* b0 = (const float2*)&bm[r0 * NT];
    const float2* b1 = (const float2*)&bm[r1 * NT];
    float mx0 = -1e30f, mx1 = -1e30f;
#pragma unroll
    for (int j = 0; j < 8; j++) {
        float2 bb0 = b0[4 * j + tq];
        float2 bb1 = b1[4 * j + tq];
        sacc[j][0] += bb0.x;
        sacc[j][1] += bb0.y;
        sacc[j][2] += bb1.x;
        sacc[j][3] += bb1.y;
        mx0 = fmaxf(mx0, fmaxf(sacc[j][0], sacc[j][1]));
        mx1 = fmaxf(mx1, fmaxf(sacc[j][2], sacc[j][3]));
    }
    mx0 = fmaxf(mx0, __shfl_xor_sync(0xffffffffu, mx0, 1));
    mx0 = fmaxf(mx0, __shfl_xor_sync(0xffffffffu, mx0, 2));
    mx1 = fmaxf(mx1, __shfl_xor_sync(0xffffffffu, mx1, 1));
    mx1 = fmaxf(mx1, __shfl_xor_sync(0xffffffffu, mx1, 2));
    float s0 = 0.f, s1 = 0.f;
#pragma unroll
    for (int j = 0; j < 8; j++) {
        sacc[j][0] = __expf(sacc[j][0] - mx0);
        sacc[j][1] = __expf(sacc[j][1] - mx0);
        sacc[j][2] = __expf(sacc[j][2] - mx1);
        sacc[j][3] = __expf(sacc[j][3] - mx1);
        s0 += sacc[j][0] + sacc[j][1];
        s1 += sacc[j][2] + sacc[j][3];
    }
    s0 += __shfl_xor_sync(0xffffffffu, s0, 1);
    s0 += __shfl_xor_sync(0xffffffffu, s0, 2);
    s1 += __shfl_xor_sync(0xffffffffu, s1, 1);
    s1 += __shfl_xor_sync(0xffffffffu, s1, 2);
    float inv0 = 1.f / s0, inv1 = 1.f / s1;

    // ---- O = P V  (V [t][d], B-frags via trans ldmatrix) ----
    float oacc[4][4] = {};
#pragma unroll
    for (int kc = 0; kc < 4; kc++) {
        uint32_t pa[4];
        pa[0] = packbf(sacc[2*kc  ][0] * inv0, sacc[2*kc  ][1] * inv0);
        pa[1] = packbf(sacc[2*kc  ][2] * inv1, sacc[2*kc  ][3] * inv1);
        pa[2] = packbf(sacc[2*kc+1][0] * inv0, sacc[2*kc+1][1] * inv0);
        pa[3] = packbf(sacc[2*kc+1][2] * inv1, sacc[2*kc+1][3] * inv1);
#pragma unroll
        for (int p = 0; p < 2; p++) {
            uint32_t t4[4];
            ldsm4t(t4, smem_u32(
                &Vs[kc * 16 + (lane & 15)][p * 16 + ((lane & 16) >> 1)]));
            mma16816(oacc[2 * p],     pa, t4);
            mma16816(oacc[2 * p + 1], pa, t4 + 2);
        }
    }

#pragma unroll
    for (int nj = 0; nj < 4; nj++) {
        int d = nh * HDD + 8 * nj + 2 * tq;
        __nv_bfloat162 v0 = __float22bfloat162_rn(make_float2(oacc[nj][0], oacc[nj][1]));
        __nv_bfloat162 v1 = __float22bfloat162_rn(make_float2(oacc[nj][2], oacc[nj][3]));
        *(__nv_bfloat162*)&g_att[(size_t)(w * NT + r0) * CC + d] = v0;
        *(__nv_bfloat162*)&g_att[(size_t)(w * NT + r1) * CC + d] = v1;
    }
}

// ---------------------------------------------------------------------------
// Launch
// ---------------------------------------------------------------------------
extern "C" void kernel_launch(void* const* d_in, const int* in_sizes, int n_in,
                              void* d_out, int out_size)
{
    const float* x       = (const float*)d_in[0];
    const float* norm1_g = (const float*)d_in[1];
    const float* norm1_b = (const float*)d_in[2];
    const float* qkv_w   = (const float*)d_in[3];
    const float* qkv_b   = (const float*)d_in[4];
    const float* proj_w  = (const float*)d_in[5];
    const float* proj_b  = (const float*)d_in[6];
    const float* rpb     = (const float*)d_in[7];
    const float* norm2_g = (const float*)d_in[8];
    const float* norm2_b = (const float*)d_in[9];
    const float* fc1_w   = (const float*)d_in[10];
    const float* fc1_b   = (const float*)d_in[11];
    const float* fc2_w   = (const float*)d_in[12];
    const float* fc2_b   = (const float*)d_in[13];
    float* out = (float*)d_out;

    setup_kernel<<<576, 256>>>(qkv_w, proj_w, fc1_w, fc2_w, rpb);

    ln_kernel<0><<<MROWS / 8, 256>>>(x, norm1_g, norm1_b);

    gemm_mma<0, 192, 576><<<dim3(9, 1024), 128>>>(qkv_b, nullptr, nullptr);

    attn_mma<<<NWIN * NHH, 128>>>();

    gemm_mma<3, 192, 192><<<dim3(3, 1024), 128>>>(proj_b, x, nullptr);

    ln_kernel<1><<<MROWS / 8, 256>>>(nullptr, norm2_g, norm2_b);

    gemm_mma<1, 192, 768><<<dim3(12, 1024), 128>>>(fc1_b, nullptr, nullptr);

    gemm_mma<2, 768, 192><<<dim3(3, 1024), 128>>>(fc2_b, nullptr, out);
}